// round 7
// baseline (speedup 1.0000x reference)
#include <cuda_runtime.h>
#include <cuda_fp16.h>

// Problem constants (fixed by the dataset)
#define BT_  1024   // B*T = 4*256
#define IN_  512
#define OUT_ 512

// Scratch: decoded fp32 operands (no device allocation allowed)
__device__ float g_x[BT_ * IN_];    // 2 MB
__device__ float g_w[OUT_ * IN_];   // 1 MB

// ---------------------------------------------------------------------------
// Kernel 1: decode pulse bits -> exact fp16 value in fp32.
// 4 elements per thread: 16x LDG.128 in flight, float4 store. HBM-bound.
// Pulse floats are exactly 0.0f or 1.0f, so bit 23 of the raw word is the bit.
// ---------------------------------------------------------------------------
__global__ void decode_kernel(const uint4* __restrict__ xp,
                              const uint4* __restrict__ wp) {
    int t = blockIdx.x * blockDim.x + threadIdx.x;
    const int NX = BT_ * IN_;
    const int NTOT = NX + OUT_ * IN_;
    int e0 = t * 4;
    if (e0 >= NTOT) return;

    const uint4* src;
    float* dst;
    int e;
    if (e0 < NX) { src = xp; dst = g_x; e = e0; }
    else         { src = wp; dst = g_w; e = e0 - NX; }

    uint4 v[16];
#pragma unroll
    for (int q = 0; q < 16; ++q) v[q] = src[(size_t)e * 4 + q];

    float4 r;
    float* rp = &r.x;
#pragma unroll
    for (int h = 0; h < 4; ++h) {
        unsigned u = 0u;
#pragma unroll
        for (int q = 0; q < 4; ++q) {
            uint4 w4 = v[h * 4 + q];
            u |= ((w4.x >> 23) & 1u) << (4 * q + 0);
            u |= ((w4.y >> 23) & 1u) << (4 * q + 1);
            u |= ((w4.z >> 23) & 1u) << (4 * q + 2);
            u |= ((w4.w >> 23) & 1u) << (4 * q + 3);
        }
        rp[h] = __half2float(__ushort_as_half((unsigned short)u));
    }
    *reinterpret_cast<float4*>(dst + e) = r;
}

// ---------------------------------------------------------------------------
// Kernel 2 (fused): bit-exact sequential-k GEMM + RNE fp16 + pulse encode.
//
// Tile 64x64, 128 threads, TM=8 x TN=4 per thread, ALL-SCALAR FFMA inner
// loop (rt=2, 3 narrow operands -> no RF even/odd bank pressure, no pack
// MOVs). Per k per thread: 2 LDS.128 (X rows) + 1 LDS.128 (W cols) + 32
// FFMA = 35 instr; per SM the fma pipe (64 cyc/k) is the binding floor,
// LDS crossbar at 48 cyc/k has slack. Double-buffered BK=16 smem with
// register prefetch of the next tile; one barrier per tile.
// ---------------------------------------------------------------------------
#define BM  64
#define BN  64
#define BK  16
#define NT  (IN_ / BK)   // 32 tiles
#define PIT 68           // smem pitch: 64 + 4 floats (rows 16B-aligned)

__device__ __forceinline__ float4 bits4(unsigned u, int s) {
    float4 f;
    f.x = __uint_as_float(((u >> (s + 0)) & 1u) * 0x3F800000u);
    f.y = __uint_as_float(((u >> (s + 1)) & 1u) * 0x3F800000u);
    f.z = __uint_as_float(((u >> (s + 2)) & 1u) * 0x3F800000u);
    f.w = __uint_as_float(((u >> (s + 3)) & 1u) * 0x3F800000u);
    return f;
}

__global__ __launch_bounds__(128) void gemm_enc_kernel(float* __restrict__ out) {
    __shared__ __align__(16) float Xs[2][BK][PIT];   // transposed: [k][m]
    __shared__ __align__(16) float Ws[2][BK][PIT];   // transposed: [k][n]

    const int tid  = threadIdx.x;
    const int row0 = blockIdx.y * BM;
    const int col0 = blockIdx.x * BN;

    const int rg = tid >> 4;    // 0..7  -> rows 8*rg .. 8*rg+7
    const int cg = tid & 15;    // 0..15 -> cols 4*cg .. 4*cg+3

    float acc[8][4];
#pragma unroll
    for (int i = 0; i < 8; ++i)
#pragma unroll
        for (int c = 0; c < 4; ++c) acc[i][c] = 0.0f;

    const float* Xg = g_x + (size_t)row0 * IN_;
    const float* Wg = g_w + (size_t)col0 * IN_;

    // fill mapping: 2 float4 per array per thread per tile
    // f = tid + i*128 (0..255): m = f>>2 (0..63), kq = f&3 (k-quad)
    float4 px[2], pw[2];

    // --- prologue: tile 0 ---
#pragma unroll
    for (int i = 0; i < 2; ++i) {
        int f = tid + i * 128;
        int m = f >> 2, kq = f & 3;
        px[i] = *reinterpret_cast<const float4*>(Xg + (size_t)m * IN_ + kq * 4);
        pw[i] = *reinterpret_cast<const float4*>(Wg + (size_t)m * IN_ + kq * 4);
    }
#pragma unroll
    for (int i = 0; i < 2; ++i) {
        int f = tid + i * 128;
        int m = f >> 2, kq = f & 3;
        float xv[4] = {px[i].x, px[i].y, px[i].z, px[i].w};
        float wv[4] = {pw[i].x, pw[i].y, pw[i].z, pw[i].w};
#pragma unroll
        for (int c = 0; c < 4; ++c) {
            Xs[0][kq * 4 + c][m] = xv[c];
            Ws[0][kq * 4 + c][m] = wv[c];
        }
    }
    __syncthreads();

    int buf = 0;
    for (int t = 0; t < NT; ++t) {
        // prefetch next tile into registers (hidden under 16 k of compute)
        if (t + 1 < NT) {
            int kt = (t + 1) * BK;
#pragma unroll
            for (int i = 0; i < 2; ++i) {
                int f = tid + i * 128;
                int m = f >> 2, kq = f & 3;
                px[i] = *reinterpret_cast<const float4*>(Xg + (size_t)m * IN_ + kt + kq * 4);
                pw[i] = *reinterpret_cast<const float4*>(Wg + (size_t)m * IN_ + kt + kq * 4);
            }
        }

        // compute: strictly ascending k for every output element, pure FFMA
#pragma unroll
        for (int k = 0; k < BK; ++k) {
            float4 xa = *reinterpret_cast<const float4*>(&Xs[buf][k][8 * rg]);
            float4 xb = *reinterpret_cast<const float4*>(&Xs[buf][k][8 * rg + 4]);
            float4 wq = *reinterpret_cast<const float4*>(&Ws[buf][k][4 * cg]);
            float xv[8] = {xa.x, xa.y, xa.z, xa.w, xb.x, xb.y, xb.z, xb.w};
            float wv[4] = {wq.x, wq.y, wq.z, wq.w};
#pragma unroll
            for (int i = 0; i < 8; ++i)
#pragma unroll
                for (int c = 0; c < 4; ++c)
                    acc[i][c] = __fmaf_rn(xv[i], wv[c], acc[i][c]);
        }

        // stage prefetched registers into the other buffer
        if (t + 1 < NT) {
#pragma unroll
            for (int i = 0; i < 2; ++i) {
                int f = tid + i * 128;
                int m = f >> 2, kq = f & 3;
                float xv[4] = {px[i].x, px[i].y, px[i].z, px[i].w};
                float wv[4] = {pw[i].x, pw[i].y, pw[i].z, pw[i].w};
#pragma unroll
                for (int c = 0; c < 4; ++c) {
                    Xs[buf ^ 1][kq * 4 + c][m] = xv[c];
                    Ws[buf ^ 1][kq * 4 + c][m] = wv[c];
                }
            }
        }
        __syncthreads();
        buf ^= 1;
    }

    // --- fused epilogue: fp32 -> fp16 (RNE) -> 16 pulse bits per output ---
    // Each thread writes 8 rows x 4 consecutive cols = 256B contiguous runs.
    const int cb = col0 + cg * 4;
#pragma unroll
    for (int i = 0; i < 8; ++i) {
        int r = row0 + 8 * rg + i;
        float4* dst = reinterpret_cast<float4*>(out + ((size_t)r * OUT_ + cb) * 16);
#pragma unroll
        for (int c = 0; c < 4; ++c) {
            unsigned u = __half_as_ushort(__float2half_rn(acc[i][c]));
#pragma unroll
            for (int q4 = 0; q4 < 4; ++q4)
                dst[c * 4 + q4] = bits4(u, 4 * q4);
        }
    }
}

// ---------------------------------------------------------------------------
extern "C" void kernel_launch(void* const* d_in, const int* in_sizes, int n_in,
                              void* d_out, int out_size) {
    const uint4* xp = (const uint4*)d_in[0];   // x_pulse [4,256,512,16]
    const uint4* wp = (const uint4*)d_in[1];   // w_pulse [512,512,16]
    float* out = (float*)d_out;                // [4,256,512,16]
    (void)in_sizes; (void)n_in; (void)out_size;

    // 1) decode both operand pulse arrays (4 elements / thread)
    const int n_thr = (BT_ * IN_ + OUT_ * IN_) / 4;   // 196608
    decode_kernel<<<(n_thr + 255) / 256, 256>>>(xp, wp);

    // 2) fused bit-exact GEMM + RNE fp16 + pulse-bit encode
    dim3 grid(OUT_ / BN, BT_ / BM);                   // (8, 16) = 128 CTAs
    gemm_enc_kernel<<<grid, 128>>>(out);
}

// round 8
// speedup vs baseline: 1.1021x; 1.1021x over previous
#include <cuda_runtime.h>
#include <cuda_fp16.h>
#include <cstdint>

// Problem constants (fixed by the dataset)
#define BT_  1024   // B*T = 4*256
#define IN_  512
#define OUT_ 512

// Scratch: decoded fp32 operands, TRANSPOSED to k-major (no cudaMalloc allowed)
__device__ float g_xT[IN_ * BT_];    // [k][m]  2 MB
__device__ float g_wT[IN_ * OUT_];   // [k][n]  1 MB

// ---------------------------------------------------------------------------
// Packed f32x2 FMA (Blackwell): two independent fp32 FMAs, each rounded
// exactly like scalar FFMA -> preserves bit-exact sequential accumulation.
// ---------------------------------------------------------------------------
__device__ __forceinline__ unsigned long long fma2(unsigned long long a,
                                                   unsigned long long b,
                                                   unsigned long long c) {
    unsigned long long d;
    asm("fma.rn.f32x2 %0, %1, %2, %3;" : "=l"(d) : "l"(a), "l"(b), "l"(c));
    return d;
}
__device__ __forceinline__ unsigned long long dup2(float v) {
    unsigned long long d;
    asm("mov.b64 %0, {%1, %1};" : "=l"(d) : "f"(v));
    return d;
}
__device__ __forceinline__ uint32_t sptr(const void* p) {
    return (uint32_t)__cvta_generic_to_shared(p);
}
__device__ __forceinline__ void cpa16(uint32_t dst, const void* src) {
    asm volatile("cp.async.cg.shared.global [%0], [%1], 16;" :: "r"(dst), "l"(src));
}

// ---------------------------------------------------------------------------
// Kernel 1: decode pulse bits -> exact fp16 value (fp32), TRANSPOSED store.
// Warp layout: each warp owns 32 rows x 16 k's. Lane l decodes row rbase+l,
// reading a contiguous 1KB pulse segment (4x LDG.128 per k); per k the warp
// stores 32 consecutive floats of g_*T[k][*] -> 128B coalesced. No smem.
// Pulse floats are exactly 0.0f or 1.0f, so bit 23 of the raw word is the bit.
// ---------------------------------------------------------------------------
__global__ void decode_kernel(const uint4* __restrict__ xp,
                              const uint4* __restrict__ wp) {
    const int gw = blockIdx.x * (blockDim.x >> 5) + (threadIdx.x >> 5);
    const int l  = threadIdx.x & 31;

    const uint4* src;
    float* dstT;
    int rbase, kbase, width;
    if (gw < 1024) {                       // x: 32 row-blocks x 32 k-blocks
        int rblk = gw >> 5, kblk = gw & 31;
        rbase = rblk * 32; kbase = kblk * 16;
        src = xp; dstT = g_xT; width = BT_;
    } else {                               // w: 16 row-blocks x 32 k-blocks
        int g2 = gw - 1024;
        int rblk = g2 >> 5, kblk = g2 & 31;
        rbase = rblk * 32; kbase = kblk * 16;
        src = wp; dstT = g_wT; width = OUT_;
    }

    const int r = rbase + l;
    const uint4* base = src + ((size_t)r * IN_ + kbase) * 4;  // 4 uint4/element

#pragma unroll 4
    for (int k = 0; k < 16; ++k) {
        uint4 v[4];
#pragma unroll
        for (int q = 0; q < 4; ++q) v[q] = base[k * 4 + q];
        unsigned u = 0u;
#pragma unroll
        for (int q = 0; q < 4; ++q) {
            u |= ((v[q].x >> 23) & 1u) << (4 * q + 0);
            u |= ((v[q].y >> 23) & 1u) << (4 * q + 1);
            u |= ((v[q].z >> 23) & 1u) << (4 * q + 2);
            u |= ((v[q].w >> 23) & 1u) << (4 * q + 3);
        }
        dstT[(size_t)(kbase + k) * width + r] =
            __half2float(__ushort_as_half((unsigned short)u));
    }
}

// ---------------------------------------------------------------------------
// Kernel 2 (fused): bit-exact sequential-k GEMM + RNE fp16 + pulse encode.
//
// Tile 64x64, 128 threads. Fills are pure cp.async 16B copies (operands are
// already k-major in GMEM): no staging registers, no STS in the hot path.
// Inner loop = proven R4 micro-tile: TM=8 x TN=4 per thread, M-paired f32x2
// (acc holds adjacent-row pairs), 3 LDS.128 + 4 dup-movs + 16 fma2 per k.
// Double-buffered BK=16 via cp.async commit/wait groups.
// ---------------------------------------------------------------------------
#define BM  64
#define BN  64
#define BK  16
#define NT  (IN_ / BK)   // 32 tiles
#define PIT 68           // smem pitch: 64 + 4 floats (272B rows, 16B-aligned)

__device__ __forceinline__ float4 bits4(unsigned u, int s) {
    float4 f;
    f.x = __uint_as_float(((u >> (s + 0)) & 1u) * 0x3F800000u);
    f.y = __uint_as_float(((u >> (s + 1)) & 1u) * 0x3F800000u);
    f.z = __uint_as_float(((u >> (s + 2)) & 1u) * 0x3F800000u);
    f.w = __uint_as_float(((u >> (s + 3)) & 1u) * 0x3F800000u);
    return f;
}

__global__ __launch_bounds__(128) void gemm_enc_kernel(float* __restrict__ out) {
    __shared__ __align__(16) float Xs[2][BK][PIT];   // k-major: [k][m]
    __shared__ __align__(16) float Ws[2][BK][PIT];   // k-major: [k][n]

    const int tid  = threadIdx.x;
    const int row0 = blockIdx.y * BM;
    const int col0 = blockIdx.x * BN;

    const int rg = tid >> 4;    // 0..7  -> rows 8*rg .. 8*rg+7
    const int cg = tid & 15;    // 0..15 -> cols 4*cg .. 4*cg+3

    // acc[p][c] = (C[8rg+2p][4cg+c], C[8rg+2p+1][4cg+c])
    unsigned long long acc[4][4] = {};

    // chunk mapping: 512 16B-chunks per tile (256 X + 256 W), 4 per thread.
    // i = 0,1 -> X chunks (j = tid + 128*i), i = 2,3 -> W chunks.
    const int jx0k = (tid + 0)   >> 4, jx0c = (tid + 0)   & 15;
    const int jx1k = (tid + 128) >> 4, jx1c = (tid + 128) & 15;

    auto fill = [&](int buf, int t) {
        const int kt = t * BK;
        // X chunks
        cpa16(sptr(&Xs[buf][jx0k][jx0c * 4]),
              g_xT + (size_t)(kt + jx0k) * BT_ + row0 + jx0c * 4);
        cpa16(sptr(&Xs[buf][jx1k][jx1c * 4]),
              g_xT + (size_t)(kt + jx1k) * BT_ + row0 + jx1c * 4);
        // W chunks (same j-mapping)
        cpa16(sptr(&Ws[buf][jx0k][jx0c * 4]),
              g_wT + (size_t)(kt + jx0k) * OUT_ + col0 + jx0c * 4);
        cpa16(sptr(&Ws[buf][jx1k][jx1c * 4]),
              g_wT + (size_t)(kt + jx1k) * OUT_ + col0 + jx1c * 4);
        asm volatile("cp.async.commit_group;");
    };

    fill(0, 0);

    int buf = 0;
    for (int t = 0; t < NT; ++t) {
        if (t + 1 < NT) {
            fill(buf ^ 1, t + 1);
            asm volatile("cp.async.wait_group 1;");   // tile t's fill done
        } else {
            asm volatile("cp.async.wait_group 0;");
        }
        __syncthreads();

        // compute: strictly ascending k for every output element
#pragma unroll
        for (int k = 0; k < BK; ++k) {
            ulonglong2 xa = *reinterpret_cast<const ulonglong2*>(&Xs[buf][k][8 * rg]);
            ulonglong2 xb = *reinterpret_cast<const ulonglong2*>(&Xs[buf][k][8 * rg + 4]);
            float4 wq = *reinterpret_cast<const float4*>(&Ws[buf][k][4 * cg]);
            unsigned long long wd[4];
            wd[0] = dup2(wq.x); wd[1] = dup2(wq.y);
            wd[2] = dup2(wq.z); wd[3] = dup2(wq.w);
            unsigned long long xr[4] = {xa.x, xa.y, xb.x, xb.y};
#pragma unroll
            for (int p = 0; p < 4; ++p)
#pragma unroll
                for (int c = 0; c < 4; ++c)
                    acc[p][c] = fma2(xr[p], wd[c], acc[p][c]);
        }
        __syncthreads();   // all reads of buf done before it is refilled
        buf ^= 1;
    }

    // --- fused epilogue: fp32 -> fp16 (RNE) -> 16 pulse bits per output ---
    // Each thread writes 8 rows x 4 consecutive cols = 256B contiguous runs.
    const int cb = col0 + cg * 4;
#pragma unroll
    for (int p = 0; p < 4; ++p) {
        unsigned short u[2][4];
#pragma unroll
        for (int c = 0; c < 4; ++c) {
            float lo, hi;
            asm("mov.b64 {%0, %1}, %2;" : "=f"(lo), "=f"(hi) : "l"(acc[p][c]));
            u[0][c] = __half_as_ushort(__float2half_rn(lo));
            u[1][c] = __half_as_ushort(__float2half_rn(hi));
        }
#pragma unroll
        for (int i = 0; i < 2; ++i) {
            int r = row0 + 8 * rg + 2 * p + i;
            float4* dst = reinterpret_cast<float4*>(out + ((size_t)r * OUT_ + cb) * 16);
#pragma unroll
            for (int c = 0; c < 4; ++c)
#pragma unroll
                for (int q4 = 0; q4 < 4; ++q4)
                    dst[c * 4 + q4] = bits4(u[i][c], 4 * q4);
        }
    }
}

// ---------------------------------------------------------------------------
extern "C" void kernel_launch(void* const* d_in, const int* in_sizes, int n_in,
                              void* d_out, int out_size) {
    const uint4* xp = (const uint4*)d_in[0];   // x_pulse [4,256,512,16]
    const uint4* wp = (const uint4*)d_in[1];   // w_pulse [512,512,16]
    float* out = (float*)d_out;                // [4,256,512,16]
    (void)in_sizes; (void)n_in; (void)out_size;

    // 1) decode + transpose: 1536 warps (1024 for x, 512 for w), 8 warps/block
    decode_kernel<<<192, 256>>>(xp, wp);

    // 2) fused bit-exact GEMM + RNE fp16 + pulse-bit encode
    dim3 grid(OUT_ / BN, BT_ / BM);            // (8, 16) = 128 CTAs
    gemm_enc_kernel<<<grid, 128>>>(out);
}